// round 1
// baseline (speedup 1.0000x reference)
#include <cuda_runtime.h>
#include <math.h>

#define N_NODES 8192
#define DEG 32
#define N_EDGES (N_NODES*DEG)
#define H 128
#define KTOT 33
#define NPB 16

// ---------------- device scratch (no allocations allowed) ----------------
__device__ unsigned char g_node_code[N_NODES];
__device__ unsigned char g_edge_code[N_EDGES];
__device__ float g_node_scalars[N_NODES];
__device__ float g_NF[8*H];
__device__ float g_Qt[8*H];
__device__ float g_Knt[8*H];
__device__ float g_Ket[8*H];
__device__ float g_Vnt[8*H];
__device__ float g_ut[8];
__device__ float g_D[64];
__device__ float g_Dself[8];
__device__ float g_M[3*H*H];
__device__ float g_T1[16*H];
__device__ float g_T2[16*H];
__device__ float g_T3[4*H];

// ---------------- codes ----------------
__global__ void k_codes(const int* __restrict__ ns, const int* __restrict__ es) {
    int i = blockIdx.x*blockDim.x + threadIdx.x;
    if (i < N_NODES)
        g_node_code[i] = (unsigned char)(ns[3*i] + 2*ns[3*i+1] + 4*ns[3*i+2]);
    if (i < N_EDGES)
        g_edge_code[i] = (unsigned char)(es[4*i] + 2*es[4*i+1] + 4*es[4*i+2] + 8*es[4*i+3]);
}

// ---------------- per-node self-loop scalar sum (warp per node) ----------------
__global__ void k_node_scalars(const int* __restrict__ src, const float* __restrict__ scalars) {
    int warp = (blockIdx.x*blockDim.x + threadIdx.x) >> 5;
    int lane = threadIdx.x & 31;
    if (warp >= N_NODES) return;
    int e = warp*DEG + lane;
    float v = (src[e] == warp) ? scalars[e] : 0.0f;
    #pragma unroll
    for (int o = 16; o; o >>= 1) v += __shfl_xor_sync(0xffffffffu, v, o);
    if (lane == 0) g_node_scalars[warp] = v;
}

__device__ __forceinline__ float blockReduce128(float v, float* red) {
    int lane = threadIdx.x & 31, w = threadIdx.x >> 5;
    #pragma unroll
    for (int o = 16; o; o >>= 1) v += __shfl_xor_sync(0xffffffffu, v, o);
    if (lane == 0) red[w] = v;
    __syncthreads();
    float r = red[0] + red[1] + red[2] + red[3];
    __syncthreads();
    return r;
}

// ---------------- 8-row node tables: NF, Qt(LN), Knt(LN), Vnt, Ket(LN), ut ----------------
__global__ void k_node_tables(
    const float* __restrict__ embV, const float* __restrict__ embR,
    const float* __restrict__ Wq, const float* __restrict__ Wk,
    const float* __restrict__ Wv, const float* __restrict__ Wek,
    const float* __restrict__ gW1, const float* __restrict__ gb1,
    const float* __restrict__ gW2, const float* __restrict__ gb2,
    const float* __restrict__ qs, const float* __restrict__ qb,
    const float* __restrict__ ks, const float* __restrict__ kb,
    const float* __restrict__ kes, const float* __restrict__ keb)
{
    __shared__ float s_in[H];
    __shared__ float red[32];
    int c = blockIdx.x, h = threadIdx.x;

    float nf = embV[(2*c)*H + h];
    g_NF[c*H + h] = nf;
    s_in[h] = nf;
    __syncthreads();

    float q = 0.f, k = 0.f, v = 0.f, hd = 0.f;
    for (int j = 0; j < H; j++) {
        float a = s_in[j];
        q  += a * Wq [j*H + h];
        k  += a * Wk [j*H + h];
        v  += a * Wv [j*H + h];
        hd += a * gW1[j*H + h];
    }
    g_Vnt[c*H + h] = v;

    // LN(q)
    float mu  = blockReduce128(q, red) * (1.0f/H);
    float dq  = q - mu;
    float var = blockReduce128(dq*dq, red) * (1.0f/H);
    g_Qt[c*H + h] = dq / sqrtf(var + 1e-5f) * qs[h] + qb[h];

    // LN(k)
    mu  = blockReduce128(k, red) * (1.0f/H);
    float dk = k - mu;
    var = blockReduce128(dk*dk, red) * (1.0f/H);
    g_Knt[c*H + h] = dk / sqrtf(var + 1e-5f) * ks[h] + kb[h];

    // gate u
    hd = fmaxf(hd + gb1[h], 0.0f);
    float dot = blockReduce128(hd * gW2[h], red);
    if (h == 0) g_ut[c] = 1.0f / (1.0f + expf(-(dot + gb2[0])));

    // Ket = LN(emb_recv[2c] @ Wek)
    __syncthreads();
    s_in[h] = embR[(2*c)*H + h];
    __syncthreads();
    float ke = 0.f;
    for (int j = 0; j < H; j++) ke += s_in[j] * Wek[j*H + h];
    mu  = blockReduce128(ke, red) * (1.0f/H);
    float dke = ke - mu;
    var = blockReduce128(dke*dke, red) * (1.0f/H);
    g_Ket[c*H + h] = dke / sqrtf(var + 1e-5f) * kes[h] + keb[h];
}

// ---------------- 8x8 logit table + 8 self logits ----------------
__global__ void k_D() {
    int t = threadIdx.x;
    const float inv = 0.08838834764831843f; // 1/sqrt(128)
    if (t < 64) {
        int cq = t >> 3, ck = t & 7;
        float d = 0.f;
        for (int j = 0; j < H; j++)
            d += g_Qt[cq*H + j] * (g_Knt[ck*H + j] + g_Ket[ck*H + j]);
        g_D[t] = d * inv;
    } else if (t < 72) {
        int c = t - 64;
        float d = 0.f;
        for (int j = 0; j < H; j++)
            d += g_Qt[c*H + j] * g_Knt[c*H + j];
        g_Dself[c] = d * inv;
    }
}

// ---------------- M = Wcomb @ Wev  (384x128) ----------------
__global__ void k_M(const float* __restrict__ Wcomb, const float* __restrict__ Wev) {
    int i = blockIdx.x, h = threadIdx.x;
    float acc = 0.f;
    for (int j = 0; j < H; j++)
        acc += __ldg(Wcomb + i*H + j) * __ldg(Wev + j*H + h);
    g_M[i*H + h] = acc;
}

// ---------------- T1/T2/T3 edgeV tables ----------------
__global__ void k_T(const float* __restrict__ embE, const float* __restrict__ embS) {
    int t = blockIdx.x, h = threadIdx.x;
    const float* row; float* out; int mb;
    if (t < 16)      { row = embE + t*H;      out = g_T1 + t*H;      mb = 0;     }
    else if (t < 32) { row = embE + (t-16)*H; out = g_T2 + (t-16)*H; mb = H*H;   }
    else             { row = embS + (t-32)*H; out = g_T3 + (t-32)*H; mb = 2*H*H; }
    float acc = 0.f;
    for (int j = 0; j < H; j++)
        acc += __ldg(row + j) * g_M[mb + j*H + h];
    out[h] = acc;
}

// ---------------- main per-node kernel ----------------
__global__ void __launch_bounds__(128) k_main(
    const int* __restrict__ src, const float* __restrict__ scalars,
    const int* __restrict__ rev, const float* __restrict__ embE,
    float* __restrict__ out_node, float* __restrict__ out_edge)
{
    __shared__ float sV[8*H], sT1[16*H], sT2[16*H], sT3[4*H], sNF[8*H], sEF[16*H];
    __shared__ float sD[64], sDself[8], sut[8];
    __shared__ float sLogit[KTOT], sZ[KTOT];
    __shared__ int   sCE[DEG], sSel[KTOT], sCnt[44], sNsel;
    __shared__ float sTau15, sTauSp, sSumExp;

    int tid = threadIdx.x;
    for (int i = tid; i < 8*H;  i += 128) { sV[i] = g_Vnt[i]; sNF[i] = g_NF[i]; }
    for (int i = tid; i < 16*H; i += 128) { sT1[i] = g_T1[i]; sT2[i] = g_T2[i]; sEF[i] = embE[i]; }
    for (int i = tid; i < 4*H;  i += 128) sT3[i] = g_T3[i];
    if (tid < 64) sD[tid] = g_D[tid];
    if (tid < 8)  { sDself[tid] = g_Dself[tid]; sut[tid] = g_ut[tid]; }
    __syncthreads();

    for (int ni = 0; ni < NPB; ni++) {
        int n  = blockIdx.x * NPB + ni;
        int cn = g_node_code[n];
        int cs = 0, ce = 0, cr = 0, st = 0;

        if (tid < DEG) {
            int e = n*DEG + tid;
            int s = src[e];
            cs = g_node_code[s];
            ce = g_edge_code[e];
            cr = g_edge_code[rev[e]];
            float sc   = scalars[e];
            float recv = g_node_scalars[n];
            float ss   = g_node_scalars[s];
            st = (sc < recv ? 1 : 0) + ((ss + sc) < recv ? 2 : 0);
            sLogit[tid + 1] = sD[cn*8 + cs];
            sCE[tid] = ce;
        }
        if (tid == 0) { sLogit[0] = sDself[cn]; sNsel = 0; }
        if (tid < 44) sCnt[tid] = 0;
        __syncthreads();

        // rank-based descending sort of 33 logits (stable)
        if (tid < KTOT) {
            float li = sLogit[tid];
            int r = 0;
            for (int j = 0; j < KTOT; j++) {
                float lj = sLogit[j];
                r += (lj > li) || (lj == li && j < tid);
            }
            sZ[r] = li;
        }
        __syncthreads();

        // serial tau pass (33 iters) on thread 0
        if (tid == 0) {
            float zmax = sZ[0];
            float cz = 0.f, cz2 = 0.f, se = 0.f;
            int c15 = 0, csp = 0;
            float tauc[KTOT], cza[KTOT];
            for (int i = 0; i < KTOT; i++) {
                float z = sZ[i];
                cz += z; cz2 += z*z;
                float kk  = (float)(i + 1);
                float mz  = cz / kk, mz2 = cz2 / kk;
                float dis = fmaxf(mz*mz - mz2 + 1.0f/kk, 0.0f);
                float tc  = mz - sqrtf(dis + 1e-8f);
                tauc[i] = tc; cza[i] = cz;
                c15 += (z > tc);
                csp += (kk*z > cz - 1.0f);
                se  += expf(z - zmax);
            }
            sTau15  = tauc[c15 - 1];
            sTauSp  = (cza[csp - 1] - 1.0f) / (float)csp;
            sSumExp = se;
        }
        __syncthreads();

        float uu = sut[cn];
        if (tid < KTOT) {
            float li    = sLogit[tid];
            float psoft = expf(li - sZ[0]) / sSumExp;
            float r15   = fmaxf(li - sTau15, 0.0f);
            float p15   = r15 * r15;
            float ps    = fmaxf(li - sTauSp, 0.0f);
            float p;
            if (uu <= 0.5f) { float w = 2.0f*uu;        p = (1.0f - w)*psoft + w*p15; }
            else            { float w = (uu-0.5f)*2.0f; p = (1.0f - w)*p15   + w*ps;  }
            int sel = p > 1e-4f;
            sSel[tid] = sel;
            if (sel) atomicAdd(&sNsel, 1);
        }
        __syncthreads();

        if (tid < DEG) {
            if (sSel[tid + 1]) {
                atomicAdd(&sCnt[cs],      1);
                atomicAdd(&sCnt[8 + ce],  1);
                atomicAdd(&sCnt[24 + cr], 1);
                atomicAdd(&sCnt[40 + st], 1);
            }
        } else if (tid == DEG) {
            if (sSel[0]) atomicAdd(&sCnt[cn], 1);
        }
        __syncthreads();

        float s = 1.0f / ((float)sNsel + 1e-9f);
        float agg = 0.f;
        #pragma unroll
        for (int c = 0; c < 8; c++)  agg += (float)sCnt[c]      * sV [c*H + tid];
        #pragma unroll
        for (int j = 0; j < 16; j++) agg += (float)sCnt[8 + j]  * sT1[j*H + tid];
        #pragma unroll
        for (int j = 0; j < 16; j++) agg += (float)sCnt[24 + j] * sT2[j*H + tid];
        #pragma unroll
        for (int j = 0; j < 4; j++)  agg += (float)sCnt[40 + j] * sT3[j*H + tid];
        agg *= s;

        out_node[n*H + tid] = sNF[cn*H + tid] + agg;
        float* oe = out_edge + (size_t)n * DEG * H + tid;
        #pragma unroll
        for (int k2 = 0; k2 < DEG; k2++)
            oe[k2*H] = sEF[sCE[k2]*H + tid] + agg;
        __syncthreads();
    }
}

// ---------------- launcher ----------------
extern "C" void kernel_launch(void* const* d_in, const int* in_sizes, int n_in,
                              void* d_out, int out_size)
{
    const int*   node_states = (const int*)  d_in[0];
    const int*   edge_states = (const int*)  d_in[1];
    const float* scalars     = (const float*)d_in[2];
    const int*   edge_index  = (const int*)  d_in[3];
    const int*   rev         = (const int*)  d_in[4];
    int b = 5;
    if (n_in > 5 && in_sizes[5] == 1) b = 6;  // skip scalar training_step if present
    const float* embV  = (const float*)d_in[b + 0];
    const float* embR  = (const float*)d_in[b + 1];
    const float* embE  = (const float*)d_in[b + 2];
    const float* embS  = (const float*)d_in[b + 3];
    const float* Wq    = (const float*)d_in[b + 4];
    const float* Wk    = (const float*)d_in[b + 5];
    const float* Wv    = (const float*)d_in[b + 6];
    const float* Wek   = (const float*)d_in[b + 7];
    const float* Wev   = (const float*)d_in[b + 8];
    const float* Wcomb = (const float*)d_in[b + 9];
    const float* gW1   = (const float*)d_in[b + 10];
    const float* gb1   = (const float*)d_in[b + 11];
    const float* gW2   = (const float*)d_in[b + 12];
    const float* gb2   = (const float*)d_in[b + 13];
    const float* lqs   = (const float*)d_in[b + 14];
    const float* lqb   = (const float*)d_in[b + 15];
    const float* lks   = (const float*)d_in[b + 16];
    const float* lkb   = (const float*)d_in[b + 17];
    const float* lkes  = (const float*)d_in[b + 18];
    const float* lkeb  = (const float*)d_in[b + 19];

    float* out = (float*)d_out;
    const int* src = edge_index;  // row 0 of (2,E)

    k_codes<<<(N_EDGES + 255)/256, 256>>>(node_states, edge_states);
    k_node_scalars<<<N_NODES/8, 256>>>(src, scalars);
    k_node_tables<<<8, 128>>>(embV, embR, Wq, Wk, Wv, Wek, gW1, gb1, gW2, gb2,
                              lqs, lqb, lks, lkb, lkes, lkeb);
    k_D<<<1, 128>>>();
    k_M<<<3*H, 128>>>(Wcomb, Wev);
    k_T<<<36, 128>>>(embE, embS);
    k_main<<<N_NODES/NPB, 128>>>(src, scalars, rev, embE,
                                 out, out + (size_t)N_NODES * H);
}

// round 2
// speedup vs baseline: 1.0664x; 1.0664x over previous
#include <cuda_runtime.h>
#include <math.h>

#define N_NODES 8192
#define DEG 32
#define N_EDGES (N_NODES*DEG)
#define H 128
#define FULLM 0xffffffffu

// ---------------- device scratch ----------------
__device__ unsigned char g_node_code[N_NODES];
__device__ unsigned char g_edge_code[N_EDGES];
__device__ float g_node_scalars[N_NODES];
__device__ float g_NF[8*H];
__device__ float g_Vnt[8*H];
__device__ float g_ut[8];
__device__ float g_D[64];
__device__ float g_Dself[8];
__device__ float g_T[36*H];   // T1(16) | T2(16) | T3(4)

// ================= k_pre: codes + per-node self-loop scalar =================
// grid: N_NODES/8 blocks of 256; warp w handles node n0+w (its 32 edges)
__global__ void k_pre(const int* __restrict__ ns, const int* __restrict__ es,
                      const int* __restrict__ src, const float* __restrict__ scalars)
{
    int tid = threadIdx.x;
    int n   = blockIdx.x * 8 + (tid >> 5);
    int lane = tid & 31;
    int e = n * DEG + lane;

    int4 ev = *(const int4*)(es + 4*e);
    g_edge_code[e] = (unsigned char)(ev.x + 2*ev.y + 4*ev.z + 8*ev.w);

    if (lane == 0)
        g_node_code[n] = (unsigned char)(ns[3*n] + 2*ns[3*n+1] + 4*ns[3*n+2]);

    float v = (src[e] == n) ? scalars[e] : 0.0f;
    #pragma unroll
    for (int o = 16; o; o >>= 1) v += __shfl_xor_sync(FULLM, v, o);
    if (lane == 0) g_node_scalars[n] = v;
}

// ================= k_tables: node tables + logit table D (1 block, 1024 thr) ===========
__shared__ float s_red[32];

__device__ __forceinline__ float groupReduce(float v, float* red, int grp, int lane, int wing) {
    #pragma unroll
    for (int o = 16; o; o >>= 1) v += __shfl_xor_sync(FULLM, v, o);
    if (lane == 0) red[grp*4 + wing] = v;
    __syncthreads();
    float r = red[grp*4] + red[grp*4+1] + red[grp*4+2] + red[grp*4+3];
    __syncthreads();
    return r;
}

__global__ void __launch_bounds__(1024) k_tables(
    const float* __restrict__ embV, const float* __restrict__ embR,
    const float* __restrict__ Wq, const float* __restrict__ Wk,
    const float* __restrict__ Wv, const float* __restrict__ Wek,
    const float* __restrict__ gW1, const float* __restrict__ gb1,
    const float* __restrict__ gW2, const float* __restrict__ gb2,
    const float* __restrict__ qs, const float* __restrict__ qb,
    const float* __restrict__ ks, const float* __restrict__ kb,
    const float* __restrict__ kes, const float* __restrict__ keb)
{
    __shared__ float red[32];
    __shared__ float sIn[8*H];      // node_fts per code
    __shared__ float sQt[8*H], sKn[8*H], sKe[8*H];

    int tid = threadIdx.x;
    int grp = tid >> 7;            // code 0..7
    int h   = tid & 127;
    int lane = tid & 31;
    int wing = (tid >> 5) & 3;     // warp within group

    float nf = embV[(2*grp)*H + h];
    g_NF[grp*H + h] = nf;
    sIn[grp*H + h] = nf;
    __syncthreads();

    float q = 0.f, k = 0.f, v = 0.f, hd = 0.f;
    #pragma unroll 4
    for (int j = 0; j < H; j++) {
        float a = sIn[grp*H + j];
        q  = fmaf(a, Wq [j*H + h], q);
        k  = fmaf(a, Wk [j*H + h], k);
        v  = fmaf(a, Wv [j*H + h], v);
        hd = fmaf(a, gW1[j*H + h], hd);
    }
    g_Vnt[grp*H + h] = v;

    float mu  = groupReduce(q, red, grp, lane, wing) * (1.0f/H);
    float dq  = q - mu;
    float var = groupReduce(dq*dq, red, grp, lane, wing) * (1.0f/H);
    sQt[grp*H + h] = dq * rsqrtf(var + 1e-5f) * qs[h] + qb[h];

    mu  = groupReduce(k, red, grp, lane, wing) * (1.0f/H);
    float dk = k - mu;
    var = groupReduce(dk*dk, red, grp, lane, wing) * (1.0f/H);
    sKn[grp*H + h] = dk * rsqrtf(var + 1e-5f) * ks[h] + kb[h];

    hd = fmaxf(hd + gb1[h], 0.0f);
    float dot = groupReduce(hd * gW2[h], red, grp, lane, wing);
    if (h == 0) g_ut[grp] = 1.0f / (1.0f + expf(-(dot + gb2[0])));

    // Ket = LN(emb_recv[2c] @ Wek)
    sIn[grp*H + h] = embR[(2*grp)*H + h];
    __syncthreads();
    float ke = 0.f;
    #pragma unroll 4
    for (int j = 0; j < H; j++)
        ke = fmaf(sIn[grp*H + j], Wek[j*H + h], ke);
    mu  = groupReduce(ke, red, grp, lane, wing) * (1.0f/H);
    float dke = ke - mu;
    var = groupReduce(dke*dke, red, grp, lane, wing) * (1.0f/H);
    sKe[grp*H + h] = dke * rsqrtf(var + 1e-5f) * kes[h] + keb[h];
    __syncthreads();

    // ---- D stage: 72 dots of length 128, warp per dot ----
    const float inv = 0.08838834764831843f; // 1/sqrt(128)
    int w = tid >> 5;  // 0..31
    for (int d = w; d < 72; d += 32) {
        float acc = 0.f;
        if (d < 64) {
            int cq = d >> 3, ck = d & 7;
            #pragma unroll
            for (int u = 0; u < 4; u++) {
                int j = lane*4 + u;
                acc = fmaf(sQt[cq*H + j], sKn[ck*H + j] + sKe[ck*H + j], acc);
            }
        } else {
            int c = d - 64;
            #pragma unroll
            for (int u = 0; u < 4; u++) {
                int j = lane*4 + u;
                acc = fmaf(sQt[c*H + j], sKn[c*H + j], acc);
            }
        }
        #pragma unroll
        for (int o = 16; o; o >>= 1) acc += __shfl_xor_sync(FULLM, acc, o);
        if (lane == 0) {
            if (d < 64) g_D[d] = acc * inv;
            else        g_Dself[d - 64] = acc * inv;
        }
    }
}

// ================= k_edgeT: T tables (1 block, 1024 thr) =================
__global__ void __launch_bounds__(1024) k_edgeT(
    const float* __restrict__ embE, const float* __restrict__ embS,
    const float* __restrict__ Wcomb, const float* __restrict__ Wev)
{
    __shared__ float sU[36*H];
    int tid = threadIdx.x;

    // stage 1: U[r][h] = in_r @ Wcomb[rowbase_r : rowbase_r+128][h]
    for (int idx = tid; idx < 36*H; idx += 1024) {
        int r = idx >> 7, h = idx & 127;
        const float* in = (r < 32) ? (embE + (r & 15)*H) : (embS + (r - 32)*H);
        int rowbase = (r < 16) ? 0 : (r < 32 ? H : 2*H);
        float acc = 0.f;
        #pragma unroll 4
        for (int j = 0; j < H; j++)
            acc = fmaf(__ldg(in + j), __ldg(Wcomb + (rowbase + j)*H + h), acc);
        sU[idx] = acc;
    }
    __syncthreads();

    // stage 2: T[r][h] = U[r] @ Wev[:,h]
    for (int idx = tid; idx < 36*H; idx += 1024) {
        int r = idx >> 7, h = idx & 127;
        float acc = 0.f;
        #pragma unroll 4
        for (int j = 0; j < H; j++)
            acc = fmaf(sU[r*H + j], __ldg(Wev + j*H + h), acc);
        g_T[idx] = acc;
    }
}

// ================= k_main: warp per node =================
__global__ void __launch_bounds__(512) k_main(
    const int* __restrict__ src, const float* __restrict__ scalars,
    const int* __restrict__ rev, const float* __restrict__ embE,
    float* __restrict__ out_node, float* __restrict__ out_edge)
{
    __shared__ float sV[8*H];     // Vnt
    __shared__ float sT[36*H];    // T1|T2|T3
    __shared__ float sNF[8*H];
    __shared__ float sEF[16*H];
    __shared__ float sD[64], sDself[8], sut[8];
    __shared__ float sL[16][36];  // raw logits per warp (33 used)
    __shared__ float sZ[16][36];  // sorted logits per warp

    int tid = threadIdx.x;
    int wid = tid >> 5;
    int lane = tid & 31;

    for (int i = tid; i < 8*H;  i += 512) { sV[i] = g_Vnt[i]; sNF[i] = g_NF[i]; }
    for (int i = tid; i < 36*H; i += 512) sT[i] = g_T[i];
    for (int i = tid; i < 16*H; i += 512) sEF[i] = embE[i];
    if (tid < 64) sD[tid] = g_D[tid];
    if (tid < 8)  { sDself[tid] = g_Dself[tid]; sut[tid] = g_ut[tid]; }
    __syncthreads();

    int n = blockIdx.x * 16 + wid;
    int cn = g_node_code[n];
    int e = n * DEG + lane;
    int s = src[e];
    int cs = g_node_code[s];
    int ce = g_edge_code[e];
    int cr = g_edge_code[rev[e]];
    float sc   = scalars[e];
    float recv = g_node_scalars[n];
    float ss   = g_node_scalars[s];
    int st = (sc < recv ? 1 : 0) + ((ss + sc) < recv ? 2 : 0);

    float li    = sD[cn*8 + cs];
    float lself = sDself[cn];

    sL[wid][lane] = li;
    __syncwarp();

    // rank (descending, stable by original index; self = index 0, edge i = index i+1)
    int r = (lself >= li) ? 1 : 0;
    #pragma unroll 8
    for (int j = 0; j < 32; j++) {
        float lj = sL[wid][j];
        r += (lj > li) || (lj == li && j < lane);
    }
    sZ[wid][r] = li;
    unsigned bs = __ballot_sync(FULLM, li > lself);
    if (lane == 0) sZ[wid][__popc(bs)] = lself;
    __syncwarp();

    float zk  = sZ[wid][lane];
    float z32 = sZ[wid][32];

    // inclusive scans of z and z^2 over positions 0..31
    float cz = zk, cz2 = zk*zk;
    #pragma unroll
    for (int o = 1; o < 32; o <<= 1) {
        float a = __shfl_up_sync(FULLM, cz,  o);
        float b = __shfl_up_sync(FULLM, cz2, o);
        if (lane >= o) { cz += a; cz2 += b; }
    }

    float kk  = (float)(lane + 1);
    float mz  = cz / kk, mz2 = cz2 / kk;
    float dis = fmaxf(mz*mz - mz2 + 1.0f/kk, 0.0f);
    float tauc = mz - sqrtf(dis + 1e-8f);
    int c15 = __popc(__ballot_sync(FULLM, zk > tauc));
    int csp = __popc(__ballot_sync(FULLM, kk*zk > cz - 1.0f));

    // position 32 (k=33)
    float czT  = __shfl_sync(FULLM, cz, 31) + z32;
    float cz2T = __shfl_sync(FULLM, cz2, 31) + z32*z32;
    float mzT  = czT * (1.0f/33.0f), mz2T = cz2T * (1.0f/33.0f);
    float disT = fmaxf(mzT*mzT - mz2T + 1.0f/33.0f, 0.0f);
    float tauc33 = mzT - sqrtf(disT + 1e-8f);
    c15 += (z32 > tauc33) ? 1 : 0;
    csp += (33.0f*z32 > czT - 1.0f) ? 1 : 0;

    float tau15 = (c15 <= 32) ? __shfl_sync(FULLM, tauc, c15 - 1) : tauc33;
    float czat  = (csp <= 32) ? __shfl_sync(FULLM, cz,   csp - 1) : czT;
    float tauSp = (czat - 1.0f) / (float)csp;

    // softmax denom
    float zmax = sZ[wid][0];
    float ex = expf(li - zmax);
    float se = ex;
    #pragma unroll
    for (int o = 16; o; o >>= 1) se += __shfl_xor_sync(FULLM, se, o);
    float exs = expf(lself - zmax);
    se += exs;

    // interpolated probs
    float u = sut[cn];
    float wlo = 2.0f*u, whi = (u - 0.5f)*2.0f;
    bool lowside = (u <= 0.5f);

    float r15 = fmaxf(li - tau15, 0.0f);
    float p15 = r15*r15;
    float psp = fmaxf(li - tauSp, 0.0f);
    float pso = ex / se;
    float p = lowside ? ((1.0f - wlo)*pso + wlo*p15)
                      : ((1.0f - whi)*p15 + whi*psp);
    bool sel = p > 1e-4f;

    float r15s = fmaxf(lself - tau15, 0.0f);
    float p15s = r15s*r15s;
    float psps = fmaxf(lself - tauSp, 0.0f);
    float psos = exs / se;
    float pS = lowside ? ((1.0f - wlo)*psos + wlo*p15s)
                       : ((1.0f - whi)*p15s + whi*psps);
    bool s0 = pS > 1e-4f;

    int nsel = __popc(__ballot_sync(FULLM, sel)) + (s0 ? 1 : 0);
    float scale = 1.0f / ((float)nsel + 1e-9f);

    // ---- aggregated value via bin counts (ballots) ----
    float4 agg = make_float4(0.f, 0.f, 0.f, 0.f);
    const float4* V4  = (const float4*)sV;
    const float4* T4  = (const float4*)sT;

    #pragma unroll
    for (int b = 0; b < 8; b++) {
        int c = __popc(__ballot_sync(FULLM, sel && (cs == b))) + ((s0 && cn == b) ? 1 : 0);
        if (c) {
            float fc = (float)c;
            float4 v = V4[b*32 + lane];
            agg.x = fmaf(fc, v.x, agg.x); agg.y = fmaf(fc, v.y, agg.y);
            agg.z = fmaf(fc, v.z, agg.z); agg.w = fmaf(fc, v.w, agg.w);
        }
    }
    #pragma unroll
    for (int b = 0; b < 16; b++) {
        int c = __popc(__ballot_sync(FULLM, sel && (ce == b)));
        if (c) {
            float fc = (float)c;
            float4 v = T4[b*32 + lane];
            agg.x = fmaf(fc, v.x, agg.x); agg.y = fmaf(fc, v.y, agg.y);
            agg.z = fmaf(fc, v.z, agg.z); agg.w = fmaf(fc, v.w, agg.w);
        }
    }
    #pragma unroll
    for (int b = 0; b < 16; b++) {
        int c = __popc(__ballot_sync(FULLM, sel && (cr == b)));
        if (c) {
            float fc = (float)c;
            float4 v = T4[(16 + b)*32 + lane];
            agg.x = fmaf(fc, v.x, agg.x); agg.y = fmaf(fc, v.y, agg.y);
            agg.z = fmaf(fc, v.z, agg.z); agg.w = fmaf(fc, v.w, agg.w);
        }
    }
    #pragma unroll
    for (int b = 0; b < 4; b++) {
        int c = __popc(__ballot_sync(FULLM, sel && (st == b)));
        if (c) {
            float fc = (float)c;
            float4 v = T4[(32 + b)*32 + lane];
            agg.x = fmaf(fc, v.x, agg.x); agg.y = fmaf(fc, v.y, agg.y);
            agg.z = fmaf(fc, v.z, agg.z); agg.w = fmaf(fc, v.w, agg.w);
        }
    }
    agg.x *= scale; agg.y *= scale; agg.z *= scale; agg.w *= scale;

    // node output
    const float4* NF4 = (const float4*)sNF;
    float4 nf = NF4[cn*32 + lane];
    float4 on = make_float4(nf.x + agg.x, nf.y + agg.y, nf.z + agg.z, nf.w + agg.w);
    ((float4*)out_node)[n*32 + lane] = on;

    // edge outputs: 32 rows
    const float4* EF4 = (const float4*)sEF;
    float4* OE = (float4*)out_edge;
    size_t base = (size_t)n * DEG * 32;
    #pragma unroll 4
    for (int j = 0; j < DEG; j++) {
        int cej = __shfl_sync(FULLM, ce, j);
        float4 ef = EF4[cej*32 + lane];
        OE[base + (size_t)j*32 + lane] =
            make_float4(ef.x + agg.x, ef.y + agg.y, ef.z + agg.z, ef.w + agg.w);
    }
}

// ---------------- launcher ----------------
extern "C" void kernel_launch(void* const* d_in, const int* in_sizes, int n_in,
                              void* d_out, int out_size)
{
    const int*   node_states = (const int*)  d_in[0];
    const int*   edge_states = (const int*)  d_in[1];
    const float* scalars     = (const float*)d_in[2];
    const int*   edge_index  = (const int*)  d_in[3];
    const int*   rev         = (const int*)  d_in[4];
    int b = 5;
    if (n_in > 5 && in_sizes[5] == 1) b = 6;  // skip training_step if present
    const float* embV  = (const float*)d_in[b + 0];
    const float* embR  = (const float*)d_in[b + 1];
    const float* embE  = (const float*)d_in[b + 2];
    const float* embS  = (const float*)d_in[b + 3];
    const float* Wq    = (const float*)d_in[b + 4];
    const float* Wk    = (const float*)d_in[b + 5];
    const float* Wv    = (const float*)d_in[b + 6];
    const float* Wek   = (const float*)d_in[b + 7];
    const float* Wev   = (const float*)d_in[b + 8];
    const float* Wcomb = (const float*)d_in[b + 9];
    const float* gW1   = (const float*)d_in[b + 10];
    const float* gb1   = (const float*)d_in[b + 11];
    const float* gW2   = (const float*)d_in[b + 12];
    const float* gb2   = (const float*)d_in[b + 13];
    const float* lqs   = (const float*)d_in[b + 14];
    const float* lqb   = (const float*)d_in[b + 15];
    const float* lks   = (const float*)d_in[b + 16];
    const float* lkb   = (const float*)d_in[b + 17];
    const float* lkes  = (const float*)d_in[b + 18];
    const float* lkeb  = (const float*)d_in[b + 19];

    float* out = (float*)d_out;
    const int* src = edge_index;  // row 0 of (2,E)

    k_pre<<<N_NODES/8, 256>>>(node_states, edge_states, src, scalars);
    k_tables<<<1, 1024>>>(embV, embR, Wq, Wk, Wv, Wek, gW1, gb1, gW2, gb2,
                          lqs, lqb, lks, lkb, lkes, lkeb);
    k_edgeT<<<1, 1024>>>(embE, embS, Wcomb, Wev);
    k_main<<<N_NODES/16, 512>>>(src, scalars, rev, embE,
                                out, out + (size_t)N_NODES * H);
}

// round 3
// speedup vs baseline: 2.5742x; 2.4141x over previous
#include <cuda_runtime.h>
#include <math.h>

#define N_NODES 8192
#define DEG 32
#define N_EDGES (N_NODES*DEG)
#define H 128
#define FULLM 0xffffffffu

// ---------------- device scratch ----------------
__device__ unsigned char g_node_code[N_NODES];
__device__ unsigned char g_edge_code[N_EDGES];
__device__ float g_node_scalars[N_NODES];
__device__ float g_NF[8*H];
__device__ float g_Vnt[8*H];
__device__ float g_ut[8];
__device__ float g_D[64];
__device__ float g_Dself[8];
__device__ float g_T[36*H];    // T1(16) | T2(16) | T3(4)
// raw (pre-LN) scratch
__device__ float g_Qr[8*H];
__device__ float g_Kr[8*H];
__device__ float g_HDr[8*H];
__device__ float g_KEr[8*H];
__device__ float g_U[36*H];

// =========================================================================
// stage1: grid = 1024 (pre) + 5 (node GEMMs) + 3 (Wcomb slices), 256 thr
// =========================================================================
__global__ void __launch_bounds__(256) k_stage1(
    const int* __restrict__ ns, const int* __restrict__ es,
    const int* __restrict__ src, const float* __restrict__ scalars,
    const float* __restrict__ embV, const float* __restrict__ embR,
    const float* __restrict__ embE, const float* __restrict__ embS,
    const float* __restrict__ Wq, const float* __restrict__ Wk,
    const float* __restrict__ Wv, const float* __restrict__ gW1,
    const float* __restrict__ Wek, const float* __restrict__ Wcomb)
{
    int bid = blockIdx.x;
    int tid = threadIdx.x;

    if (bid < 1024) {
        // ---- pre: codes + per-node self-loop scalar ----
        int n = bid * 8 + (tid >> 5);
        int lane = tid & 31;
        int e = n * DEG + lane;

        int4 ev = *(const int4*)(es + 4*e);
        g_edge_code[e] = (unsigned char)(ev.x + 2*ev.y + 4*ev.z + 8*ev.w);

        if (lane == 0)
            g_node_code[n] = (unsigned char)(ns[3*n] + 2*ns[3*n+1] + 4*ns[3*n+2]);

        float v = (src[e] == n) ? scalars[e] : 0.0f;
        #pragma unroll
        for (int o = 16; o; o >>= 1) v += __shfl_xor_sync(FULLM, v, o);
        if (lane == 0) g_node_scalars[n] = v;
        return;
    }

    if (bid < 1029) {
        // ---- node GEMMs: out[c][h] = node_fts[c] @ W[:,h], c=0..7 ----
        int m = bid - 1024;              // 0:Wq 1:Wk 2:Wv 3:gW1 4:Wek
        const float* W;
        float* out;
        const float* embIn;
        switch (m) {
            case 0: W = Wq;  out = g_Qr;  embIn = embV; break;
            case 1: W = Wk;  out = g_Kr;  embIn = embV; break;
            case 2: W = Wv;  out = g_Vnt; embIn = embV; break;
            case 3: W = gW1; out = g_HDr; embIn = embV; break;
            default: W = Wek; out = g_KEr; embIn = embR; break;
        }
        __shared__ float sIn[8*H];
        for (int i = tid; i < 8*H; i += 256)
            sIn[i] = embIn[(2*(i >> 7))*H + (i & 127)];
        // also stash NF once (from the Wq block)
        if (m == 0)
            for (int i = tid; i < 8*H; i += 256)
                g_NF[i] = embV[(2*(i >> 7))*H + (i & 127)];
        __syncthreads();

        int h = tid & 127;
        int cg = (tid >> 7) * 4;         // codes cg..cg+3
        float a0 = 0.f, a1 = 0.f, a2 = 0.f, a3 = 0.f;
        #pragma unroll 4
        for (int j = 0; j < H; j++) {
            float w = __ldg(W + j*H + h);
            a0 = fmaf(sIn[(cg+0)*H + j], w, a0);
            a1 = fmaf(sIn[(cg+1)*H + j], w, a1);
            a2 = fmaf(sIn[(cg+2)*H + j], w, a2);
            a3 = fmaf(sIn[(cg+3)*H + j], w, a3);
        }
        out[(cg+0)*H + h] = a0;
        out[(cg+1)*H + h] = a1;
        out[(cg+2)*H + h] = a2;
        out[(cg+3)*H + h] = a3;
        return;
    }

    // ---- Wcomb slices: U[r] = in_r @ Wcomb_slice ----
    {
        int s = bid - 1029;              // 0:T1(embE,rows0-127) 1:T2(embE,128-255) 2:T3(embS,256-383)
        int nrows = (s == 2) ? 4 : 16;
        const float* in = (s == 2) ? embS : embE;
        int rowoff = s * H;
        int uoff = (s == 0) ? 0 : (s == 1 ? 16 : 32);

        __shared__ float sIn[16*H];
        for (int i = tid; i < nrows*H; i += 256) sIn[i] = in[i];
        __syncthreads();

        int h = tid & 127;
        int half = tid >> 7;
        int rpt = (s == 2) ? 2 : 8;
        int r0 = half * rpt;

        float acc[8];
        #pragma unroll
        for (int r = 0; r < 8; r++) acc[r] = 0.f;
        #pragma unroll 2
        for (int j = 0; j < H; j++) {
            float w = __ldg(Wcomb + (rowoff + j)*H + h);
            #pragma unroll
            for (int r = 0; r < 8; r++)
                if (r < rpt) acc[r] = fmaf(sIn[(r0 + r)*H + j], w, acc[r]);
        }
        for (int r = 0; r < rpt; r++)
            g_U[(uoff + r0 + r)*H + h] = acc[r];
        return;
    }
}

// =========================================================================
// stage2: grid = 6 blocks, 1024 thr.
//   block 0: LN(Q/K/KE) + gate u + logit tables D/Dself
//   blocks 1..5: T[row] = U[row] @ Wev  (8 rows each)
// =========================================================================
__device__ __forceinline__ float groupReduce(float v, float* red, int grp, int lane, int wing) {
    #pragma unroll
    for (int o = 16; o; o >>= 1) v += __shfl_xor_sync(FULLM, v, o);
    if (lane == 0) red[grp*4 + wing] = v;
    __syncthreads();
    float r = red[grp*4] + red[grp*4+1] + red[grp*4+2] + red[grp*4+3];
    __syncthreads();
    return r;
}

__global__ void __launch_bounds__(1024) k_stage2(
    const float* __restrict__ Wev,
    const float* __restrict__ gb1, const float* __restrict__ gW2,
    const float* __restrict__ gb2,
    const float* __restrict__ qs, const float* __restrict__ qb,
    const float* __restrict__ ks, const float* __restrict__ kb,
    const float* __restrict__ kes, const float* __restrict__ keb)
{
    int tid = threadIdx.x;

    if (blockIdx.x > 0) {
        // ---- T rows ----
        int row = (blockIdx.x - 1) * 8 + (tid >> 7);
        int h = tid & 127;
        if (row < 36) {
            float acc = 0.f;
            #pragma unroll 4
            for (int j = 0; j < H; j++)
                acc = fmaf(g_U[row*H + j], __ldg(Wev + j*H + h), acc);
            g_T[row*H + h] = acc;
        }
        return;
    }

    // ---- block 0: LN + u + D ----
    __shared__ float red[32];
    __shared__ float sQt[8*H], sKn[8*H], sKe[8*H];

    int grp = tid >> 7;
    int h   = tid & 127;
    int lane = tid & 31;
    int wing = (tid >> 5) & 3;

    float q = g_Qr[grp*H + h];
    float mu  = groupReduce(q, red, grp, lane, wing) * (1.0f/H);
    float dq  = q - mu;
    float var = groupReduce(dq*dq, red, grp, lane, wing) * (1.0f/H);
    sQt[grp*H + h] = dq * rsqrtf(var + 1e-5f) * qs[h] + qb[h];

    float k = g_Kr[grp*H + h];
    mu  = groupReduce(k, red, grp, lane, wing) * (1.0f/H);
    float dk = k - mu;
    var = groupReduce(dk*dk, red, grp, lane, wing) * (1.0f/H);
    sKn[grp*H + h] = dk * rsqrtf(var + 1e-5f) * ks[h] + kb[h];

    float hd = fmaxf(g_HDr[grp*H + h] + gb1[h], 0.0f);
    float dot = groupReduce(hd * gW2[h], red, grp, lane, wing);
    if (h == 0) g_ut[grp] = 1.0f / (1.0f + expf(-(dot + gb2[0])));

    float ke = g_KEr[grp*H + h];
    mu  = groupReduce(ke, red, grp, lane, wing) * (1.0f/H);
    float dke = ke - mu;
    var = groupReduce(dke*dke, red, grp, lane, wing) * (1.0f/H);
    sKe[grp*H + h] = dke * rsqrtf(var + 1e-5f) * kes[h] + keb[h];
    __syncthreads();

    // ---- D: 72 dots of length 128, warp per dot ----
    const float inv = 0.08838834764831843f; // 1/sqrt(128)
    int w = tid >> 5;
    for (int d = w; d < 72; d += 32) {
        float acc = 0.f;
        if (d < 64) {
            int cq = d >> 3, ck = d & 7;
            #pragma unroll
            for (int u = 0; u < 4; u++) {
                int j = lane*4 + u;
                acc = fmaf(sQt[cq*H + j], sKn[ck*H + j] + sKe[ck*H + j], acc);
            }
        } else {
            int c = d - 64;
            #pragma unroll
            for (int u = 0; u < 4; u++) {
                int j = lane*4 + u;
                acc = fmaf(sQt[c*H + j], sKn[c*H + j], acc);
            }
        }
        #pragma unroll
        for (int o = 16; o; o >>= 1) acc += __shfl_xor_sync(FULLM, acc, o);
        if (lane == 0) {
            if (d < 64) g_D[d] = acc * inv;
            else        g_Dself[d - 64] = acc * inv;
        }
    }
}

// ================= k_main: warp per node =================
__global__ void __launch_bounds__(512) k_main(
    const int* __restrict__ src, const float* __restrict__ scalars,
    const int* __restrict__ rev, const float* __restrict__ embE,
    float* __restrict__ out_node, float* __restrict__ out_edge)
{
    __shared__ float sV[8*H];
    __shared__ float sT[36*H];
    __shared__ float sNF[8*H];
    __shared__ float sEF[16*H];
    __shared__ float sD[64], sDself[8], sut[8];
    __shared__ float sL[16][36];
    __shared__ float sZ[16][36];

    int tid = threadIdx.x;
    int wid = tid >> 5;
    int lane = tid & 31;

    for (int i = tid; i < 8*H;  i += 512) { sV[i] = g_Vnt[i]; sNF[i] = g_NF[i]; }
    for (int i = tid; i < 36*H; i += 512) sT[i] = g_T[i];
    for (int i = tid; i < 16*H; i += 512) sEF[i] = embE[i];
    if (tid < 64) sD[tid] = g_D[tid];
    if (tid < 8)  { sDself[tid] = g_Dself[tid]; sut[tid] = g_ut[tid]; }
    __syncthreads();

    int n = blockIdx.x * 16 + wid;
    int cn = g_node_code[n];
    int e = n * DEG + lane;
    int s = src[e];
    int cs = g_node_code[s];
    int ce = g_edge_code[e];
    int cr = g_edge_code[rev[e]];
    float sc   = scalars[e];
    float recv = g_node_scalars[n];
    float ss   = g_node_scalars[s];
    int st = (sc < recv ? 1 : 0) + ((ss + sc) < recv ? 2 : 0);

    float li    = sD[cn*8 + cs];
    float lself = sDself[cn];

    sL[wid][lane] = li;
    __syncwarp();

    // rank (descending, stable; self = index 0, edge i = index i+1)
    int r = (lself >= li) ? 1 : 0;
    #pragma unroll 8
    for (int j = 0; j < 32; j++) {
        float lj = sL[wid][j];
        r += (lj > li) || (lj == li && j < lane);
    }
    sZ[wid][r] = li;
    unsigned bs = __ballot_sync(FULLM, li > lself);
    if (lane == 0) sZ[wid][__popc(bs)] = lself;
    __syncwarp();

    float zk  = sZ[wid][lane];
    float z32 = sZ[wid][32];

    float cz = zk, cz2 = zk*zk;
    #pragma unroll
    for (int o = 1; o < 32; o <<= 1) {
        float a = __shfl_up_sync(FULLM, cz,  o);
        float b = __shfl_up_sync(FULLM, cz2, o);
        if (lane >= o) { cz += a; cz2 += b; }
    }

    float kk  = (float)(lane + 1);
    float mz  = cz / kk, mz2 = cz2 / kk;
    float dis = fmaxf(mz*mz - mz2 + 1.0f/kk, 0.0f);
    float tauc = mz - sqrtf(dis + 1e-8f);
    int c15 = __popc(__ballot_sync(FULLM, zk > tauc));
    int csp = __popc(__ballot_sync(FULLM, kk*zk > cz - 1.0f));

    float czT  = __shfl_sync(FULLM, cz, 31) + z32;
    float cz2T = __shfl_sync(FULLM, cz2, 31) + z32*z32;
    float mzT  = czT * (1.0f/33.0f), mz2T = cz2T * (1.0f/33.0f);
    float disT = fmaxf(mzT*mzT - mz2T + 1.0f/33.0f, 0.0f);
    float tauc33 = mzT - sqrtf(disT + 1e-8f);
    c15 += (z32 > tauc33) ? 1 : 0;
    csp += (33.0f*z32 > czT - 1.0f) ? 1 : 0;

    float tau15 = (c15 <= 32) ? __shfl_sync(FULLM, tauc, c15 - 1) : tauc33;
    float czat  = (csp <= 32) ? __shfl_sync(FULLM, cz,   csp - 1) : czT;
    float tauSp = (czat - 1.0f) / (float)csp;

    float zmax = sZ[wid][0];
    float ex = expf(li - zmax);
    float se = ex;
    #pragma unroll
    for (int o = 16; o; o >>= 1) se += __shfl_xor_sync(FULLM, se, o);
    float exs = expf(lself - zmax);
    se += exs;

    float u = sut[cn];
    float wlo = 2.0f*u, whi = (u - 0.5f)*2.0f;
    bool lowside = (u <= 0.5f);

    float r15 = fmaxf(li - tau15, 0.0f);
    float p15 = r15*r15;
    float psp = fmaxf(li - tauSp, 0.0f);
    float pso = ex / se;
    float p = lowside ? ((1.0f - wlo)*pso + wlo*p15)
                      : ((1.0f - whi)*p15 + whi*psp);
    bool sel = p > 1e-4f;

    float r15s = fmaxf(lself - tau15, 0.0f);
    float p15s = r15s*r15s;
    float psps = fmaxf(lself - tauSp, 0.0f);
    float psos = exs / se;
    float pS = lowside ? ((1.0f - wlo)*psos + wlo*p15s)
                       : ((1.0f - whi)*p15s + whi*psps);
    bool s0 = pS > 1e-4f;

    int nsel = __popc(__ballot_sync(FULLM, sel)) + (s0 ? 1 : 0);
    float scale = 1.0f / ((float)nsel + 1e-9f);

    float4 agg = make_float4(0.f, 0.f, 0.f, 0.f);
    const float4* V4  = (const float4*)sV;
    const float4* T4  = (const float4*)sT;

    #pragma unroll
    for (int b = 0; b < 8; b++) {
        int c = __popc(__ballot_sync(FULLM, sel && (cs == b))) + ((s0 && cn == b) ? 1 : 0);
        if (c) {
            float fc = (float)c;
            float4 v = V4[b*32 + lane];
            agg.x = fmaf(fc, v.x, agg.x); agg.y = fmaf(fc, v.y, agg.y);
            agg.z = fmaf(fc, v.z, agg.z); agg.w = fmaf(fc, v.w, agg.w);
        }
    }
    #pragma unroll
    for (int b = 0; b < 16; b++) {
        int c = __popc(__ballot_sync(FULLM, sel && (ce == b)));
        if (c) {
            float fc = (float)c;
            float4 v = T4[b*32 + lane];
            agg.x = fmaf(fc, v.x, agg.x); agg.y = fmaf(fc, v.y, agg.y);
            agg.z = fmaf(fc, v.z, agg.z); agg.w = fmaf(fc, v.w, agg.w);
        }
    }
    #pragma unroll
    for (int b = 0; b < 16; b++) {
        int c = __popc(__ballot_sync(FULLM, sel && (cr == b)));
        if (c) {
            float fc = (float)c;
            float4 v = T4[(16 + b)*32 + lane];
            agg.x = fmaf(fc, v.x, agg.x); agg.y = fmaf(fc, v.y, agg.y);
            agg.z = fmaf(fc, v.z, agg.z); agg.w = fmaf(fc, v.w, agg.w);
        }
    }
    #pragma unroll
    for (int b = 0; b < 4; b++) {
        int c = __popc(__ballot_sync(FULLM, sel && (st == b)));
        if (c) {
            float fc = (float)c;
            float4 v = T4[(32 + b)*32 + lane];
            agg.x = fmaf(fc, v.x, agg.x); agg.y = fmaf(fc, v.y, agg.y);
            agg.z = fmaf(fc, v.z, agg.z); agg.w = fmaf(fc, v.w, agg.w);
        }
    }
    agg.x *= scale; agg.y *= scale; agg.z *= scale; agg.w *= scale;

    const float4* NF4 = (const float4*)sNF;
    float4 nf = NF4[cn*32 + lane];
    ((float4*)out_node)[n*32 + lane] =
        make_float4(nf.x + agg.x, nf.y + agg.y, nf.z + agg.z, nf.w + agg.w);

    const float4* EF4 = (const float4*)sEF;
    float4* OE = (float4*)out_edge;
    size_t base = (size_t)n * DEG * 32;
    #pragma unroll 4
    for (int j = 0; j < DEG; j++) {
        int cej = __shfl_sync(FULLM, ce, j);
        float4 ef = EF4[cej*32 + lane];
        OE[base + (size_t)j*32 + lane] =
            make_float4(ef.x + agg.x, ef.y + agg.y, ef.z + agg.z, ef.w + agg.w);
    }
}

// ---------------- launcher ----------------
extern "C" void kernel_launch(void* const* d_in, const int* in_sizes, int n_in,
                              void* d_out, int out_size)
{
    const int*   node_states = (const int*)  d_in[0];
    const int*   edge_states = (const int*)  d_in[1];
    const float* scalars     = (const float*)d_in[2];
    const int*   edge_index  = (const int*)  d_in[3];
    const int*   rev         = (const int*)  d_in[4];
    int b = 5;
    if (n_in > 5 && in_sizes[5] == 1) b = 6;  // skip training_step if present
    const float* embV  = (const float*)d_in[b + 0];
    const float* embR  = (const float*)d_in[b + 1];
    const float* embE  = (const float*)d_in[b + 2];
    const float* embS  = (const float*)d_in[b + 3];
    const float* Wq    = (const float*)d_in[b + 4];
    const float* Wk    = (const float*)d_in[b + 5];
    const float* Wv    = (const float*)d_in[b + 6];
    const float* Wek   = (const float*)d_in[b + 7];
    const float* Wev   = (const float*)d_in[b + 8];
    const float* Wcomb = (const float*)d_in[b + 9];
    const float* gW1   = (const float*)d_in[b + 10];
    const float* gb1   = (const float*)d_in[b + 11];
    const float* gW2   = (const float*)d_in[b + 12];
    const float* gb2   = (const float*)d_in[b + 13];
    const float* lqs   = (const float*)d_in[b + 14];
    const float* lqb   = (const float*)d_in[b + 15];
    const float* lks   = (const float*)d_in[b + 16];
    const float* lkb   = (const float*)d_in[b + 17];
    const float* lkes  = (const float*)d_in[b + 18];
    const float* lkeb  = (const float*)d_in[b + 19];

    float* out = (float*)d_out;
    const int* src = edge_index;  // row 0 of (2,E)

    k_stage1<<<1032, 256>>>(node_states, edge_states, src, scalars,
                            embV, embR, embE, embS,
                            Wq, Wk, Wv, gW1, Wek, Wcomb);
    k_stage2<<<6, 1024>>>(Wev, gb1, gW2, gb2,
                          lqs, lqb, lks, lkb, lkes, lkeb);
    k_main<<<N_NODES/16, 512>>>(src, scalars, rev, embE,
                                out, out + (size_t)N_NODES * H);
}

// round 4
// speedup vs baseline: 3.4986x; 1.3591x over previous
#include <cuda_runtime.h>
#include <math.h>

#define N_NODES 8192
#define DEG 32
#define N_EDGES (N_NODES*DEG)
#define H 128
#define FULLM 0xffffffffu

// ---------------- device scratch ----------------
__device__ unsigned char g_node_code[N_NODES];
__device__ unsigned char g_edge_code[N_EDGES];
__device__ float g_node_scalars[N_NODES];
__device__ float g_NF[8*H];
__device__ float g_Vnt[8*H];
__device__ float g_ut[8];
__device__ float g_D[64];
__device__ float g_Dself[8];
__device__ float g_T[36*H];    // T1(16) | T2(16) | T3(4)
// raw (pre-LN) scratch
__device__ float g_Qr[8*H];
__device__ float g_Kr[8*H];
__device__ float g_HDr[8*H];
__device__ float g_KEr[8*H];
__device__ float g_U[36*H];

// =========================================================================
// stage1: grid = 1024 (pre) + 76 (fine-grained GEMM tasks), 256 thr
//   task 0..39 : node GEMMs  (m = task>>3 in {Wq,Wk,Wv,gW1,Wek}, c = task&7)
//   task 40..75: U rows      (r = task-40; Wcomb slice GEMV)
//   each dot of length 128 is split 2-way across thread halves.
// =========================================================================
__global__ void __launch_bounds__(256) k_stage1(
    const int* __restrict__ ns, const int* __restrict__ es,
    const int* __restrict__ src, const float* __restrict__ scalars,
    const float* __restrict__ embV, const float* __restrict__ embR,
    const float* __restrict__ embE, const float* __restrict__ embS,
    const float* __restrict__ Wq, const float* __restrict__ Wk,
    const float* __restrict__ Wv, const float* __restrict__ gW1,
    const float* __restrict__ Wek, const float* __restrict__ Wcomb)
{
    int bid = blockIdx.x;
    int tid = threadIdx.x;

    if (bid < 1024) {
        // ---- pre: codes + per-node self-loop scalar ----
        int n = bid * 8 + (tid >> 5);
        int lane = tid & 31;
        int e = n * DEG + lane;

        int4 ev = *(const int4*)(es + 4*e);
        g_edge_code[e] = (unsigned char)(ev.x + 2*ev.y + 4*ev.z + 8*ev.w);

        if (lane == 0)
            g_node_code[n] = (unsigned char)(ns[3*n] + 2*ns[3*n+1] + 4*ns[3*n+2]);

        float v = (src[e] == n) ? scalars[e] : 0.0f;
        #pragma unroll
        for (int o = 16; o; o >>= 1) v += __shfl_xor_sync(FULLM, v, o);
        if (lane == 0) g_node_scalars[n] = v;
        return;
    }

    // ---- fine-grained GEMV tasks ----
    __shared__ float sP[256];
    int task = bid - 1024;
    int h  = tid & 127;
    int kh = tid >> 7;          // 0 or 1: k-half

    const float* W;
    const float* in;
    float* out;

    if (task < 40) {
        int m = task >> 3, c = task & 7;
        switch (m) {
            case 0: W = Wq;  out = g_Qr  + c*H; break;
            case 1: W = Wk;  out = g_Kr  + c*H; break;
            case 2: W = Wv;  out = g_Vnt + c*H; break;
            case 3: W = gW1; out = g_HDr + c*H; break;
            default: W = Wek; out = g_KEr + c*H; break;
        }
        in = ((m == 4) ? embR : embV) + (2*c)*H;
        if (m == 0 && kh == 0) g_NF[c*H + h] = in[h];
    } else {
        int r = task - 40;
        int rowoff = (r < 16) ? 0 : (r < 32 ? H : 2*H);
        W = Wcomb + (size_t)rowoff * H;
        in = (r < 32) ? (embE + (r & 15)*H) : (embS + (r - 32)*H);
        out = g_U + r*H;
    }

    float acc = 0.f;
    const float* Wp = W + (size_t)(kh*64)*H + h;
    const float* ip = in + kh*64;
    #pragma unroll 16
    for (int jj = 0; jj < 64; jj++)
        acc = fmaf(__ldg(ip + jj), __ldg(Wp + (size_t)jj*H), acc);

    sP[tid] = acc;
    __syncthreads();
    if (kh == 0) out[h] = sP[h] + sP[128 + h];
}

// =========================================================================
// stage2: grid = 37 blocks, 1024 thr.
//   block 0  : LN(Q/K/KE) + gate u + logit tables D/Dself
//   blocks >0: T[row] = U[row] @ Wev  (one row per block, 8-way k-split)
// =========================================================================
__device__ __forceinline__ float groupReduce(float v, float* red, int grp, int lane, int wing) {
    #pragma unroll
    for (int o = 16; o; o >>= 1) v += __shfl_xor_sync(FULLM, v, o);
    if (lane == 0) red[grp*4 + wing] = v;
    __syncthreads();
    float r = red[grp*4] + red[grp*4+1] + red[grp*4+2] + red[grp*4+3];
    __syncthreads();
    return r;
}

__global__ void __launch_bounds__(1024) k_stage2(
    const float* __restrict__ Wev,
    const float* __restrict__ gb1, const float* __restrict__ gW2,
    const float* __restrict__ gb2,
    const float* __restrict__ qs, const float* __restrict__ qb,
    const float* __restrict__ ks, const float* __restrict__ kb,
    const float* __restrict__ kes, const float* __restrict__ keb)
{
    int tid = threadIdx.x;

    if (blockIdx.x > 0) {
        // ---- one T row, 8-way k-split ----
        __shared__ float sP[1024];
        int row = blockIdx.x - 1;
        int h  = tid & 127;
        int kseg = tid >> 7;              // 0..7
        float acc = 0.f;
        const float* up = g_U + row*H + kseg*16;
        const float* wp = Wev + (size_t)(kseg*16)*H + h;
        #pragma unroll
        for (int jj = 0; jj < 16; jj++)
            acc = fmaf(up[jj], __ldg(wp + (size_t)jj*H), acc);
        sP[tid] = acc;
        __syncthreads();
        if (kseg == 0) {
            float t = 0.f;
            #pragma unroll
            for (int s = 0; s < 8; s++) t += sP[s*128 + h];
            g_T[row*H + h] = t;
        }
        return;
    }

    // ---- block 0: LN + u + D ----
    __shared__ float red[32];
    __shared__ float sQt[8*H], sKn[8*H], sKe[8*H];

    int grp = tid >> 7;
    int h   = tid & 127;
    int lane = tid & 31;
    int wing = (tid >> 5) & 3;

    float q = g_Qr[grp*H + h];
    float mu  = groupReduce(q, red, grp, lane, wing) * (1.0f/H);
    float dq  = q - mu;
    float var = groupReduce(dq*dq, red, grp, lane, wing) * (1.0f/H);
    sQt[grp*H + h] = dq * rsqrtf(var + 1e-5f) * qs[h] + qb[h];

    float k = g_Kr[grp*H + h];
    mu  = groupReduce(k, red, grp, lane, wing) * (1.0f/H);
    float dk = k - mu;
    var = groupReduce(dk*dk, red, grp, lane, wing) * (1.0f/H);
    sKn[grp*H + h] = dk * rsqrtf(var + 1e-5f) * ks[h] + kb[h];

    float hd = fmaxf(g_HDr[grp*H + h] + gb1[h], 0.0f);
    float dot = groupReduce(hd * gW2[h], red, grp, lane, wing);
    if (h == 0) g_ut[grp] = 1.0f / (1.0f + expf(-(dot + gb2[0])));

    float ke = g_KEr[grp*H + h];
    mu  = groupReduce(ke, red, grp, lane, wing) * (1.0f/H);
    float dke = ke - mu;
    var = groupReduce(dke*dke, red, grp, lane, wing) * (1.0f/H);
    sKe[grp*H + h] = dke * rsqrtf(var + 1e-5f) * kes[h] + keb[h];
    __syncthreads();

    // ---- D: 72 dots of length 128, warp per dot ----
    const float inv = 0.08838834764831843f; // 1/sqrt(128)
    int w = tid >> 5;
    for (int d = w; d < 72; d += 32) {
        float acc = 0.f;
        if (d < 64) {
            int cq = d >> 3, ck = d & 7;
            #pragma unroll
            for (int u = 0; u < 4; u++) {
                int j = lane*4 + u;
                acc = fmaf(sQt[cq*H + j], sKn[ck*H + j] + sKe[ck*H + j], acc);
            }
        } else {
            int c = d - 64;
            #pragma unroll
            for (int u = 0; u < 4; u++) {
                int j = lane*4 + u;
                acc = fmaf(sQt[c*H + j], sKn[c*H + j], acc);
            }
        }
        #pragma unroll
        for (int o = 16; o; o >>= 1) acc += __shfl_xor_sync(FULLM, acc, o);
        if (lane == 0) {
            if (d < 64) g_D[d] = acc * inv;
            else        g_Dself[d - 64] = acc * inv;
        }
    }
}

// ================= k_main: warp per node =================
__global__ void __launch_bounds__(512) k_main(
    const int* __restrict__ src, const float* __restrict__ scalars,
    const int* __restrict__ rev, const float* __restrict__ embE,
    float* __restrict__ out_node, float* __restrict__ out_edge)
{
    __shared__ float sV[8*H];
    __shared__ float sT[36*H];
    __shared__ float sNF[8*H];
    __shared__ float sEF[16*H];
    __shared__ float sD[64], sDself[8], sut[8];
    __shared__ float sL[16][36];
    __shared__ float sZ[16][36];

    int tid = threadIdx.x;
    int wid = tid >> 5;
    int lane = tid & 31;

    for (int i = tid; i < 8*H;  i += 512) { sV[i] = g_Vnt[i]; sNF[i] = g_NF[i]; }
    for (int i = tid; i < 36*H; i += 512) sT[i] = g_T[i];
    for (int i = tid; i < 16*H; i += 512) sEF[i] = embE[i];
    if (tid < 64) sD[tid] = g_D[tid];
    if (tid < 8)  { sDself[tid] = g_Dself[tid]; sut[tid] = g_ut[tid]; }
    __syncthreads();

    int n = blockIdx.x * 16 + wid;
    int cn = g_node_code[n];
    int e = n * DEG + lane;
    int s = src[e];
    int cs = g_node_code[s];
    int ce = g_edge_code[e];
    int cr = g_edge_code[rev[e]];
    float sc   = scalars[e];
    float recv = g_node_scalars[n];
    float ss   = g_node_scalars[s];
    int st = (sc < recv ? 1 : 0) + ((ss + sc) < recv ? 2 : 0);

    float li    = sD[cn*8 + cs];
    float lself = sDself[cn];

    sL[wid][lane] = li;
    __syncwarp();

    // rank (descending, stable; self = index 0, edge i = index i+1)
    int r = (lself >= li) ? 1 : 0;
    #pragma unroll 8
    for (int j = 0; j < 32; j++) {
        float lj = sL[wid][j];
        r += (lj > li) || (lj == li && j < lane);
    }
    sZ[wid][r] = li;
    unsigned bs = __ballot_sync(FULLM, li > lself);
    if (lane == 0) sZ[wid][__popc(bs)] = lself;
    __syncwarp();

    float zk  = sZ[wid][lane];
    float z32 = sZ[wid][32];

    float cz = zk, cz2 = zk*zk;
    #pragma unroll
    for (int o = 1; o < 32; o <<= 1) {
        float a = __shfl_up_sync(FULLM, cz,  o);
        float b = __shfl_up_sync(FULLM, cz2, o);
        if (lane >= o) { cz += a; cz2 += b; }
    }

    float kk  = (float)(lane + 1);
    float mz  = cz / kk, mz2 = cz2 / kk;
    float dis = fmaxf(mz*mz - mz2 + 1.0f/kk, 0.0f);
    float tauc = mz - sqrtf(dis + 1e-8f);
    int c15 = __popc(__ballot_sync(FULLM, zk > tauc));
    int csp = __popc(__ballot_sync(FULLM, kk*zk > cz - 1.0f));

    float czT  = __shfl_sync(FULLM, cz, 31) + z32;
    float cz2T = __shfl_sync(FULLM, cz2, 31) + z32*z32;
    float mzT  = czT * (1.0f/33.0f), mz2T = cz2T * (1.0f/33.0f);
    float disT = fmaxf(mzT*mzT - mz2T + 1.0f/33.0f, 0.0f);
    float tauc33 = mzT - sqrtf(disT + 1e-8f);
    c15 += (z32 > tauc33) ? 1 : 0;
    csp += (33.0f*z32 > czT - 1.0f) ? 1 : 0;

    float tau15 = (c15 <= 32) ? __shfl_sync(FULLM, tauc, c15 - 1) : tauc33;
    float czat  = (csp <= 32) ? __shfl_sync(FULLM, cz,   csp - 1) : czT;
    float tauSp = (czat - 1.0f) / (float)csp;

    float zmax = sZ[wid][0];
    float ex = expf(li - zmax);
    float se = ex;
    #pragma unroll
    for (int o = 16; o; o >>= 1) se += __shfl_xor_sync(FULLM, se, o);
    float exs = expf(lself - zmax);
    se += exs;

    float u = sut[cn];
    float wlo = 2.0f*u, whi = (u - 0.5f)*2.0f;
    bool lowside = (u <= 0.5f);

    float r15 = fmaxf(li - tau15, 0.0f);
    float p15 = r15*r15;
    float psp = fmaxf(li - tauSp, 0.0f);
    float pso = ex / se;
    float p = lowside ? ((1.0f - wlo)*pso + wlo*p15)
                      : ((1.0f - whi)*p15 + whi*psp);
    bool sel = p > 1e-4f;

    float r15s = fmaxf(lself - tau15, 0.0f);
    float p15s = r15s*r15s;
    float psps = fmaxf(lself - tauSp, 0.0f);
    float psos = exs / se;
    float pS = lowside ? ((1.0f - wlo)*psos + wlo*p15s)
                       : ((1.0f - whi)*p15s + whi*psps);
    bool s0 = pS > 1e-4f;

    int nsel = __popc(__ballot_sync(FULLM, sel)) + (s0 ? 1 : 0);
    float scale = 1.0f / ((float)nsel + 1e-9f);

    float4 agg = make_float4(0.f, 0.f, 0.f, 0.f);
    const float4* V4  = (const float4*)sV;
    const float4* T4  = (const float4*)sT;

    #pragma unroll
    for (int b = 0; b < 8; b++) {
        int c = __popc(__ballot_sync(FULLM, sel && (cs == b))) + ((s0 && cn == b) ? 1 : 0);
        if (c) {
            float fc = (float)c;
            float4 v = V4[b*32 + lane];
            agg.x = fmaf(fc, v.x, agg.x); agg.y = fmaf(fc, v.y, agg.y);
            agg.z = fmaf(fc, v.z, agg.z); agg.w = fmaf(fc, v.w, agg.w);
        }
    }
    #pragma unroll
    for (int b = 0; b < 16; b++) {
        int c = __popc(__ballot_sync(FULLM, sel && (ce == b)));
        if (c) {
            float fc = (float)c;
            float4 v = T4[b*32 + lane];
            agg.x = fmaf(fc, v.x, agg.x); agg.y = fmaf(fc, v.y, agg.y);
            agg.z = fmaf(fc, v.z, agg.z); agg.w = fmaf(fc, v.w, agg.w);
        }
    }
    #pragma unroll
    for (int b = 0; b < 16; b++) {
        int c = __popc(__ballot_sync(FULLM, sel && (cr == b)));
        if (c) {
            float fc = (float)c;
            float4 v = T4[(16 + b)*32 + lane];
            agg.x = fmaf(fc, v.x, agg.x); agg.y = fmaf(fc, v.y, agg.y);
            agg.z = fmaf(fc, v.z, agg.z); agg.w = fmaf(fc, v.w, agg.w);
        }
    }
    #pragma unroll
    for (int b = 0; b < 4; b++) {
        int c = __popc(__ballot_sync(FULLM, sel && (st == b)));
        if (c) {
            float fc = (float)c;
            float4 v = T4[(32 + b)*32 + lane];
            agg.x = fmaf(fc, v.x, agg.x); agg.y = fmaf(fc, v.y, agg.y);
            agg.z = fmaf(fc, v.z, agg.z); agg.w = fmaf(fc, v.w, agg.w);
        }
    }
    agg.x *= scale; agg.y *= scale; agg.z *= scale; agg.w *= scale;

    const float4* NF4 = (const float4*)sNF;
    float4 nf = NF4[cn*32 + lane];
    ((float4*)out_node)[n*32 + lane] =
        make_float4(nf.x + agg.x, nf.y + agg.y, nf.z + agg.z, nf.w + agg.w);

    const float4* EF4 = (const float4*)sEF;
    float4* OE = (float4*)out_edge;
    size_t base = (size_t)n * DEG * 32;
    #pragma unroll 4
    for (int j = 0; j < DEG; j++) {
        int cej = __shfl_sync(FULLM, ce, j);
        float4 ef = EF4[cej*32 + lane];
        OE[base + (size_t)j*32 + lane] =
            make_float4(ef.x + agg.x, ef.y + agg.y, ef.z + agg.z, ef.w + agg.w);
    }
}

// ---------------- launcher ----------------
extern "C" void kernel_launch(void* const* d_in, const int* in_sizes, int n_in,
                              void* d_out, int out_size)
{
    const int*   node_states = (const int*)  d_in[0];
    const int*   edge_states = (const int*)  d_in[1];
    const float* scalars     = (const float*)d_in[2];
    const int*   edge_index  = (const int*)  d_in[3];
    const int*   rev         = (const int*)  d_in[4];
    int b = 5;
    if (n_in > 5 && in_sizes[5] == 1) b = 6;  // skip training_step if present
    const float* embV  = (const float*)d_in[b + 0];
    const float* embR  = (const float*)d_in[b + 1];
    const float* embE  = (const float*)d_in[b + 2];
    const float* embS  = (const float*)d_in[b + 3];
    const float* Wq    = (const float*)d_in[b + 4];
    const float* Wk    = (const float*)d_in[b + 5];
    const float* Wv    = (const float*)d_in[b + 6];
    const float* Wek   = (const float*)d_in[b + 7];
    const float* Wev   = (const float*)d_in[b + 8];
    const float* Wcomb = (const float*)d_in[b + 9];
    const float* gW1   = (const float*)d_in[b + 10];
    const float* gb1   = (const float*)d_in[b + 11];
    const float* gW2   = (const float*)d_in[b + 12];
    const float* gb2   = (const float*)d_in[b + 13];
    const float* lqs   = (const float*)d_in[b + 14];
    const float* lqb   = (const float*)d_in[b + 15];
    const float* lks   = (const float*)d_in[b + 16];
    const float* lkb   = (const float*)d_in[b + 17];
    const float* lkes  = (const float*)d_in[b + 18];
    const float* lkeb  = (const float*)d_in[b + 19];

    float* out = (float*)d_out;
    const int* src = edge_index;  // row 0 of (2,E)

    k_stage1<<<1024 + 76, 256>>>(node_states, edge_states, src, scalars,
                                 embV, embR, embE, embS,
                                 Wq, Wk, Wv, gW1, Wek, Wcomb);
    k_stage2<<<37, 1024>>>(Wev, gb1, gW2, gb2,
                           lqs, lqb, lks, lkb, lkes, lkeb);
    k_main<<<N_NODES/16, 512>>>(src, scalars, rev, embE,
                                out, out + (size_t)N_NODES * H);
}

// round 5
// speedup vs baseline: 4.8684x; 1.3915x over previous
#include <cuda_runtime.h>
#include <math.h>

#define N_NODES 8192
#define DEG 32
#define N_EDGES (N_NODES*DEG)
#define H 128
#define FULLM 0xffffffffu

// ---------------- device scratch ----------------
__device__ unsigned char g_node_code[N_NODES];
__device__ unsigned char g_edge_code[N_EDGES];
__device__ float g_node_scalars[N_NODES];
__device__ float g_NF[8*H];
__device__ float g_Vnt[8*H];
__device__ float g_ut[8];
__device__ float g_D[64];
__device__ float g_Dself[8];
__device__ float g_T[36*H];    // T1(16) | T2(16) | T3(4)
// raw (pre-LN) scratch
__device__ float g_Qr[8*H];
__device__ float g_Kr[8*H];
__device__ float g_HDr[8*H];
__device__ float g_KEr[8*H];
__device__ float g_U[36*H];

// =========================================================================
// k_A: grid = 128 (pre; 2 nodes/warp) + 76 (GEMV tasks, 8-way k-split), 1024 thr
// =========================================================================
__global__ void __launch_bounds__(1024) k_A(
    const int* __restrict__ ns, const int* __restrict__ es,
    const int* __restrict__ src, const float* __restrict__ scalars,
    const float* __restrict__ embV, const float* __restrict__ embR,
    const float* __restrict__ embE, const float* __restrict__ embS,
    const float* __restrict__ Wq, const float* __restrict__ Wk,
    const float* __restrict__ Wv, const float* __restrict__ gW1,
    const float* __restrict__ Wek, const float* __restrict__ Wcomb)
{
    int bid = blockIdx.x;
    int tid = threadIdx.x;

    if (bid < 128) {
        // ---- pre: codes + per-node self-loop scalar, 2 nodes per warp ----
        int wid = tid >> 5;
        int lane = tid & 31;
        #pragma unroll
        for (int rep = 0; rep < 2; rep++) {
            int n = bid * 64 + wid * 2 + rep;
            int e = n * DEG + lane;

            int4 ev = *(const int4*)(es + 4*e);
            g_edge_code[e] = (unsigned char)(ev.x + 2*ev.y + 4*ev.z + 8*ev.w);

            if (lane == 0)
                g_node_code[n] = (unsigned char)(ns[3*n] + 2*ns[3*n+1] + 4*ns[3*n+2]);

            float v = (src[e] == n) ? scalars[e] : 0.0f;
            #pragma unroll
            for (int o = 16; o; o >>= 1) v += __shfl_xor_sync(FULLM, v, o);
            if (lane == 0) g_node_scalars[n] = v;
        }
        return;
    }

    // ---- GEMV tasks: task 0..39 node GEMMs, 40..75 U rows; 8-way k-split ----
    __shared__ float sP[1024];
    int task = bid - 128;
    int h    = tid & 127;
    int kseg = tid >> 7;          // 0..7

    const float* W;
    const float* in;
    float* out;

    if (task < 40) {
        int m = task >> 3, c = task & 7;
        switch (m) {
            case 0: W = Wq;  out = g_Qr  + c*H; break;
            case 1: W = Wk;  out = g_Kr  + c*H; break;
            case 2: W = Wv;  out = g_Vnt + c*H; break;
            case 3: W = gW1; out = g_HDr + c*H; break;
            default: W = Wek; out = g_KEr + c*H; break;
        }
        in = ((m == 4) ? embR : embV) + (2*c)*H;
        if (m == 0 && kseg == 0) g_NF[c*H + h] = __ldg(in + h);
    } else {
        int r = task - 40;
        int rowoff = (r < 16) ? 0 : (r < 32 ? H : 2*H);
        W = Wcomb + (size_t)rowoff * H;
        in = (r < 32) ? (embE + (r & 15)*H) : (embS + (r - 32)*H);
        out = g_U + r*H;
    }

    float acc = 0.f;
    const float* Wp = W + (size_t)(kseg*16)*H + h;
    const float* ip = in + kseg*16;
    #pragma unroll
    for (int jj = 0; jj < 16; jj++)
        acc = fmaf(__ldg(ip + jj), __ldg(Wp + (size_t)jj*H), acc);

    sP[tid] = acc;
    __syncthreads();
    if (kseg == 0) {
        float t = 0.f;
        #pragma unroll
        for (int s = 0; s < 8; s++) t += sP[s*128 + h];
        out[h] = t;
    }
}

// =========================================================================
// k_B: grid = 37 blocks, 1024 thr.
//   block 0  : warp-per-code LN (Q/K/KE) + gate u, 1 barrier, then D table
//   blocks >0: T[row] = U[row] @ Wev  (one row per block, 8-way k-split)
// =========================================================================
__global__ void __launch_bounds__(1024) k_B(
    const float* __restrict__ Wev,
    const float* __restrict__ gb1, const float* __restrict__ gW2,
    const float* __restrict__ gb2,
    const float* __restrict__ qs, const float* __restrict__ qb,
    const float* __restrict__ ks, const float* __restrict__ kb,
    const float* __restrict__ kes, const float* __restrict__ keb)
{
    int tid = threadIdx.x;

    if (blockIdx.x > 0) {
        __shared__ float sP[1024];
        int row = blockIdx.x - 1;
        int h  = tid & 127;
        int kseg = tid >> 7;
        float acc = 0.f;
        const float* up = g_U + row*H + kseg*16;
        const float* wp = Wev + (size_t)(kseg*16)*H + h;
        #pragma unroll
        for (int jj = 0; jj < 16; jj++)
            acc = fmaf(up[jj], __ldg(wp + (size_t)jj*H), acc);
        sP[tid] = acc;
        __syncthreads();
        if (kseg == 0) {
            float t = 0.f;
            #pragma unroll
            for (int s = 0; s < 8; s++) t += sP[s*128 + h];
            g_T[row*H + h] = t;
        }
        return;
    }

    // ---- block 0 ----
    __shared__ float sQt[8*H], sKn[8*H], sKe[8*H];

    int wid = tid >> 5;
    int lane = tid & 31;

    if (wid < 8) {
        int c = wid;
        // ---- LN(Q) ----
        float4 x = ((const float4*)(g_Qr + c*H))[lane];
        float sum = x.x + x.y + x.z + x.w;
        #pragma unroll
        for (int o = 16; o; o >>= 1) sum += __shfl_xor_sync(FULLM, sum, o);
        float mu = sum * (1.0f/H);
        float4 d = make_float4(x.x - mu, x.y - mu, x.z - mu, x.w - mu);
        float v2 = d.x*d.x + d.y*d.y + d.z*d.z + d.w*d.w;
        #pragma unroll
        for (int o = 16; o; o >>= 1) v2 += __shfl_xor_sync(FULLM, v2, o);
        float rs = rsqrtf(v2 * (1.0f/H) + 1e-5f);
        float4 s4 = ((const float4*)qs)[lane];
        float4 b4 = ((const float4*)qb)[lane];
        ((float4*)(sQt + c*H))[lane] = make_float4(
            d.x*rs*s4.x + b4.x, d.y*rs*s4.y + b4.y,
            d.z*rs*s4.z + b4.z, d.w*rs*s4.w + b4.w);

        // ---- LN(K) ----
        x = ((const float4*)(g_Kr + c*H))[lane];
        sum = x.x + x.y + x.z + x.w;
        #pragma unroll
        for (int o = 16; o; o >>= 1) sum += __shfl_xor_sync(FULLM, sum, o);
        mu = sum * (1.0f/H);
        d = make_float4(x.x - mu, x.y - mu, x.z - mu, x.w - mu);
        v2 = d.x*d.x + d.y*d.y + d.z*d.z + d.w*d.w;
        #pragma unroll
        for (int o = 16; o; o >>= 1) v2 += __shfl_xor_sync(FULLM, v2, o);
        rs = rsqrtf(v2 * (1.0f/H) + 1e-5f);
        s4 = ((const float4*)ks)[lane];
        b4 = ((const float4*)kb)[lane];
        ((float4*)(sKn + c*H))[lane] = make_float4(
            d.x*rs*s4.x + b4.x, d.y*rs*s4.y + b4.y,
            d.z*rs*s4.z + b4.z, d.w*rs*s4.w + b4.w);

        // ---- gate u ----
        float4 hd = ((const float4*)(g_HDr + c*H))[lane];
        float4 gb = ((const float4*)gb1)[lane];
        float4 gw = ((const float4*)gW2)[lane];
        float dot =
            fmaxf(hd.x + gb.x, 0.f)*gw.x + fmaxf(hd.y + gb.y, 0.f)*gw.y +
            fmaxf(hd.z + gb.z, 0.f)*gw.z + fmaxf(hd.w + gb.w, 0.f)*gw.w;
        #pragma unroll
        for (int o = 16; o; o >>= 1) dot += __shfl_xor_sync(FULLM, dot, o);
        if (lane == 0) g_ut[c] = 1.0f / (1.0f + expf(-(dot + __ldg(gb2))));

        // ---- LN(KE) ----
        x = ((const float4*)(g_KEr + c*H))[lane];
        sum = x.x + x.y + x.z + x.w;
        #pragma unroll
        for (int o = 16; o; o >>= 1) sum += __shfl_xor_sync(FULLM, sum, o);
        mu = sum * (1.0f/H);
        d = make_float4(x.x - mu, x.y - mu, x.z - mu, x.w - mu);
        v2 = d.x*d.x + d.y*d.y + d.z*d.z + d.w*d.w;
        #pragma unroll
        for (int o = 16; o; o >>= 1) v2 += __shfl_xor_sync(FULLM, v2, o);
        rs = rsqrtf(v2 * (1.0f/H) + 1e-5f);
        s4 = ((const float4*)kes)[lane];
        b4 = ((const float4*)keb)[lane];
        ((float4*)(sKe + c*H))[lane] = make_float4(
            d.x*rs*s4.x + b4.x, d.y*rs*s4.y + b4.y,
            d.z*rs*s4.z + b4.z, d.w*rs*s4.w + b4.w);
    }
    __syncthreads();

    // ---- D: 72 dots of length 128, warp per dot ----
    const float inv = 0.08838834764831843f; // 1/sqrt(128)
    for (int dd = wid; dd < 72; dd += 32) {
        float acc = 0.f;
        if (dd < 64) {
            int cq = dd >> 3, ck = dd & 7;
            #pragma unroll
            for (int u = 0; u < 4; u++) {
                int j = lane*4 + u;
                acc = fmaf(sQt[cq*H + j], sKn[ck*H + j] + sKe[ck*H + j], acc);
            }
        } else {
            int c = dd - 64;
            #pragma unroll
            for (int u = 0; u < 4; u++) {
                int j = lane*4 + u;
                acc = fmaf(sQt[c*H + j], sKn[c*H + j], acc);
            }
        }
        #pragma unroll
        for (int o = 16; o; o >>= 1) acc += __shfl_xor_sync(FULLM, acc, o);
        if (lane == 0) {
            if (dd < 64) g_D[dd] = acc * inv;
            else         g_Dself[dd - 64] = acc * inv;
        }
    }
}

// ================= k_main: warp per node =================
__global__ void __launch_bounds__(512) k_main(
    const int* __restrict__ src, const float* __restrict__ scalars,
    const int* __restrict__ rev, const float* __restrict__ embE,
    float* __restrict__ out_node, float* __restrict__ out_edge)
{
    __shared__ float sV[8*H];
    __shared__ float sT[36*H];
    __shared__ float sNF[8*H];
    __shared__ float sEF[16*H];
    __shared__ float sD[64], sDself[8], sut[8];
    __shared__ float sL[16][36];
    __shared__ float sZ[16][36];

    int tid = threadIdx.x;
    int wid = tid >> 5;
    int lane = tid & 31;

    for (int i = tid; i < 8*H;  i += 512) { sV[i] = g_Vnt[i]; sNF[i] = g_NF[i]; }
    for (int i = tid; i < 36*H; i += 512) sT[i] = g_T[i];
    for (int i = tid; i < 16*H; i += 512) sEF[i] = embE[i];
    if (tid < 64) sD[tid] = g_D[tid];
    if (tid < 8)  { sDself[tid] = g_Dself[tid]; sut[tid] = g_ut[tid]; }
    __syncthreads();

    int n = blockIdx.x * 16 + wid;
    int cn = g_node_code[n];
    int e = n * DEG + lane;
    int s = src[e];
    int cs = g_node_code[s];
    int ce = g_edge_code[e];
    int cr = g_edge_code[rev[e]];
    float sc   = scalars[e];
    float recv = g_node_scalars[n];
    float ss   = g_node_scalars[s];
    int st = (sc < recv ? 1 : 0) + ((ss + sc) < recv ? 2 : 0);

    float li    = sD[cn*8 + cs];
    float lself = sDself[cn];

    sL[wid][lane] = li;
    __syncwarp();

    int r = (lself >= li) ? 1 : 0;
    #pragma unroll 8
    for (int j = 0; j < 32; j++) {
        float lj = sL[wid][j];
        r += (lj > li) || (lj == li && j < lane);
    }
    sZ[wid][r] = li;
    unsigned bs = __ballot_sync(FULLM, li > lself);
    if (lane == 0) sZ[wid][__popc(bs)] = lself;
    __syncwarp();

    float zk  = sZ[wid][lane];
    float z32 = sZ[wid][32];

    float cz = zk, cz2 = zk*zk;
    #pragma unroll
    for (int o = 1; o < 32; o <<= 1) {
        float a = __shfl_up_sync(FULLM, cz,  o);
        float b = __shfl_up_sync(FULLM, cz2, o);
        if (lane >= o) { cz += a; cz2 += b; }
    }

    float kk  = (float)(lane + 1);
    float mz  = cz / kk, mz2 = cz2 / kk;
    float dis = fmaxf(mz*mz - mz2 + 1.0f/kk, 0.0f);
    float tauc = mz - sqrtf(dis + 1e-8f);
    int c15 = __popc(__ballot_sync(FULLM, zk > tauc));
    int csp = __popc(__ballot_sync(FULLM, kk*zk > cz - 1.0f));

    float czT  = __shfl_sync(FULLM, cz, 31) + z32;
    float cz2T = __shfl_sync(FULLM, cz2, 31) + z32*z32;
    float mzT  = czT * (1.0f/33.0f), mz2T = cz2T * (1.0f/33.0f);
    float disT = fmaxf(mzT*mzT - mz2T + 1.0f/33.0f, 0.0f);
    float tauc33 = mzT - sqrtf(disT + 1e-8f);
    c15 += (z32 > tauc33) ? 1 : 0;
    csp += (33.0f*z32 > czT - 1.0f) ? 1 : 0;

    float tau15 = (c15 <= 32) ? __shfl_sync(FULLM, tauc, c15 - 1) : tauc33;
    float czat  = (csp <= 32) ? __shfl_sync(FULLM, cz,   csp - 1) : czT;
    float tauSp = (czat - 1.0f) / (float)csp;

    float zmax = sZ[wid][0];
    float ex = expf(li - zmax);
    float se = ex;
    #pragma unroll
    for (int o = 16; o; o >>= 1) se += __shfl_xor_sync(FULLM, se, o);
    float exs = expf(lself - zmax);
    se += exs;

    float u = sut[cn];
    float wlo = 2.0f*u, whi = (u - 0.5f)*2.0f;
    bool lowside = (u <= 0.5f);

    float r15 = fmaxf(li - tau15, 0.0f);
    float p15 = r15*r15;
    float psp = fmaxf(li - tauSp, 0.0f);
    float pso = ex / se;
    float p = lowside ? ((1.0f - wlo)*pso + wlo*p15)
                      : ((1.0f - whi)*p15 + whi*psp);
    bool sel = p > 1e-4f;

    float r15s = fmaxf(lself - tau15, 0.0f);
    float p15s = r15s*r15s;
    float psps = fmaxf(lself - tauSp, 0.0f);
    float psos = exs / se;
    float pS = lowside ? ((1.0f - wlo)*psos + wlo*p15s)
                       : ((1.0f - whi)*p15s + whi*psps);
    bool s0 = pS > 1e-4f;

    int nsel = __popc(__ballot_sync(FULLM, sel)) + (s0 ? 1 : 0);
    float scale = 1.0f / ((float)nsel + 1e-9f);

    float4 agg = make_float4(0.f, 0.f, 0.f, 0.f);
    const float4* V4  = (const float4*)sV;
    const float4* T4  = (const float4*)sT;

    #pragma unroll
    for (int b = 0; b < 8; b++) {
        int c = __popc(__ballot_sync(FULLM, sel && (cs == b))) + ((s0 && cn == b) ? 1 : 0);
        if (c) {
            float fc = (float)c;
            float4 v = V4[b*32 + lane];
            agg.x = fmaf(fc, v.x, agg.x); agg.y = fmaf(fc, v.y, agg.y);
            agg.z = fmaf(fc, v.z, agg.z); agg.w = fmaf(fc, v.w, agg.w);
        }
    }
    #pragma unroll
    for (int b = 0; b < 16; b++) {
        int c = __popc(__ballot_sync(FULLM, sel && (ce == b)));
        if (c) {
            float fc = (float)c;
            float4 v = T4[b*32 + lane];
            agg.x = fmaf(fc, v.x, agg.x); agg.y = fmaf(fc, v.y, agg.y);
            agg.z = fmaf(fc, v.z, agg.z); agg.w = fmaf(fc, v.w, agg.w);
        }
    }
    #pragma unroll
    for (int b = 0; b < 16; b++) {
        int c = __popc(__ballot_sync(FULLM, sel && (cr == b)));
        if (c) {
            float fc = (float)c;
            float4 v = T4[(16 + b)*32 + lane];
            agg.x = fmaf(fc, v.x, agg.x); agg.y = fmaf(fc, v.y, agg.y);
            agg.z = fmaf(fc, v.z, agg.z); agg.w = fmaf(fc, v.w, agg.w);
        }
    }
    #pragma unroll
    for (int b = 0; b < 4; b++) {
        int c = __popc(__ballot_sync(FULLM, sel && (st == b)));
        if (c) {
            float fc = (float)c;
            float4 v = T4[(32 + b)*32 + lane];
            agg.x = fmaf(fc, v.x, agg.x); agg.y = fmaf(fc, v.y, agg.y);
            agg.z = fmaf(fc, v.z, agg.z); agg.w = fmaf(fc, v.w, agg.w);
        }
    }
    agg.x *= scale; agg.y *= scale; agg.z *= scale; agg.w *= scale;

    const float4* NF4 = (const float4*)sNF;
    float4 nf = NF4[cn*32 + lane];
    ((float4*)out_node)[n*32 + lane] =
        make_float4(nf.x + agg.x, nf.y + agg.y, nf.z + agg.z, nf.w + agg.w);

    const float4* EF4 = (const float4*)sEF;
    float4* OE = (float4*)out_edge;
    size_t base = (size_t)n * DEG * 32;
    #pragma unroll 4
    for (int j = 0; j < DEG; j++) {
        int cej = __shfl_sync(FULLM, ce, j);
        float4 ef = EF4[cej*32 + lane];
        OE[base + (size_t)j*32 + lane] =
            make_float4(ef.x + agg.x, ef.y + agg.y, ef.z + agg.z, ef.w + agg.w);
    }
}

// ---------------- launcher ----------------
extern "C" void kernel_launch(void* const* d_in, const int* in_sizes, int n_in,
                              void* d_out, int out_size)
{
    const int*   node_states = (const int*)  d_in[0];
    const int*   edge_states = (const int*)  d_in[1];
    const float* scalars     = (const float*)d_in[2];
    const int*   edge_index  = (const int*)  d_in[3];
    const int*   rev         = (const int*)  d_in[4];
    int b = 5;
    if (n_in > 5 && in_sizes[5] == 1) b = 6;  // skip training_step if present
    const float* embV  = (const float*)d_in[b + 0];
    const float* embR  = (const float*)d_in[b + 1];
    const float* embE  = (const float*)d_in[b + 2];
    const float* embS  = (const float*)d_in[b + 3];
    const float* Wq    = (const float*)d_in[b + 4];
    const float* Wk    = (const float*)d_in[b + 5];
    const float* Wv    = (const float*)d_in[b + 6];
    const float* Wek   = (const float*)d_in[b + 7];
    const float* Wev   = (const float*)d_in[b + 8];
    const float* Wcomb = (const float*)d_in[b + 9];
    const float* gW1   = (const float*)d_in[b + 10];
    const float* gb1   = (const float*)d_in[b + 11];
    const float* gW2   = (const float*)d_in[b + 12];
    const float* gb2   = (const float*)d_in[b + 13];
    const float* lqs   = (const float*)d_in[b + 14];
    const float* lqb   = (const float*)d_in[b + 15];
    const float* lks   = (const float*)d_in[b + 16];
    const float* lkb   = (const float*)d_in[b + 17];
    const float* lkes  = (const float*)d_in[b + 18];
    const float* lkeb  = (const float*)d_in[b + 19];

    float* out = (float*)d_out;
    const int* src = edge_index;  // row 0 of (2,E)

    k_A<<<128 + 76, 1024>>>(node_states, edge_states, src, scalars,
                            embV, embR, embE, embS,
                            Wq, Wk, Wv, gW1, Wek, Wcomb);
    k_B<<<37, 1024>>>(Wev, gb1, gW2, gb2,
                      lqs, lqb, lks, lkb, lkes, lkeb);
    k_main<<<N_NODES/16, 512>>>(src, scalars, rev, embE,
                                out, out + (size_t)N_NODES * H);
}